// round 1
// baseline (speedup 1.0000x reference)
#include <cuda_runtime.h>
#include <cuda_bf16.h>
#include <math.h>

// Problem constants (fixed shapes for PPIModel_6957847020274)
#define H_DIM 2
#define L_LAYERS 4
#define R_RELS 16
#define B_BASES 8
#define N_NODES 1000000
#define E_EDGES 16000000

// Scratch (allocation-free rule: __device__ globals)
__device__ float2 g_x[N_NODES];
__device__ float2 g_h[N_NODES];
__device__ float2 g_skip[N_NODES];
__device__ float  g_W[L_LAYERS * R_RELS * 4];   // [l][r][i*2+o]
__device__ float  g_acc;

// ---------------------------------------------------------------------------
// Precompute W[l][r] = sum_b comp[l,r,b] * V[l,b]   (tiny: 64 threads)
// V: [L,B,H,H] row-major; comp: [L,R,B]
__global__ void compute_weights_kernel(const float* __restrict__ V,
                                       const float* __restrict__ comp) {
    int tid = threadIdx.x;          // 0..63 = l*R + r
    if (tid >= L_LAYERS * R_RELS) return;
    int l = tid / R_RELS;
    int r = tid % R_RELS;
    float w[4] = {0.f, 0.f, 0.f, 0.f};
    #pragma unroll
    for (int b = 0; b < B_BASES; b++) {
        float c = comp[(l * R_RELS + r) * B_BASES + b];
        const float* v = V + ((l * B_BASES + b) * 4);
        w[0] += c * v[0];
        w[1] += c * v[1];
        w[2] += c * v[2];
        w[3] += c * v[3];
    }
    #pragma unroll
    for (int o = 0; o < 4; o++) g_W[tid * 4 + o] = w[o];
}

// ---------------------------------------------------------------------------
// Copy features into x and skip (layer-0 inputs)
__global__ void init_x_kernel(const float2* __restrict__ feat) {
    int i = blockIdx.x * blockDim.x + threadIdx.x;
    if (i >= N_NODES) return;
    float2 f = feat[i];
    g_x[i] = f;
    g_skip[i] = f;
}

// h[n] = bias[l]  (also zeroes the dot accumulator when asked)
__global__ void init_h_kernel(const float* __restrict__ bias, int l) {
    int i = blockIdx.x * blockDim.x + threadIdx.x;
    if (i == 0) g_acc = 0.f;
    if (i >= N_NODES) return;
    float2 b = make_float2(bias[2 * l], bias[2 * l + 1]);
    g_h[i] = b;
}

// ---------------------------------------------------------------------------
// Edge kernel: 4 edges per thread, vectorized streaming loads,
// gather x[src] (L2-resident), float2 atomic scatter to h[dst].
__global__ void edge_kernel(const int4* __restrict__ src4,
                            const int4* __restrict__ dst4,
                            const int4* __restrict__ type4,
                            const float4* __restrict__ norm4,
                            int l) {
    __shared__ float sW[R_RELS * 4];
    if (threadIdx.x < R_RELS * 4)
        sW[threadIdx.x] = g_W[l * R_RELS * 4 + threadIdx.x];
    __syncthreads();

    int i = blockIdx.x * blockDim.x + threadIdx.x;
    if (i >= E_EDGES / 4) return;

    int4   s  = src4[i];
    int4   d  = dst4[i];
    int4   t  = type4[i];
    float4 nm = norm4[i];

    int   ss[4] = {s.x, s.y, s.z, s.w};
    int   dd[4] = {d.x, d.y, d.z, d.w};
    int   tt[4] = {t.x, t.y, t.z, t.w};
    float nn[4] = {nm.x, nm.y, nm.z, nm.w};

    #pragma unroll
    for (int k = 0; k < 4; k++) {
        float2 xs = g_x[ss[k]];
        const float* w = &sW[tt[k] * 4];
        float m0 = (xs.x * w[0] + xs.y * w[2]) * nn[k];
        float m1 = (xs.x * w[1] + xs.y * w[3]) * nn[k];
        atomicAdd(&g_h[dd[k]], make_float2(m0, m1));
    }
}

// ---------------------------------------------------------------------------
// Node epilogue: relu (layers 0..2), skip connection on odd layers.
__global__ void node_kernel(int l) {
    int i = blockIdx.x * blockDim.x + threadIdx.x;
    if (i >= N_NODES) return;
    float2 h = g_h[i];
    if (l < L_LAYERS - 1) {
        h.x = fmaxf(h.x, 0.f);
        h.y = fmaxf(h.y, 0.f);
    }
    if (l & 1) {
        float2 sk = g_skip[i];
        h.x += sk.x;
        h.y += sk.y;
        g_skip[i] = h;
    }
    g_x[i] = h;
}

// ---------------------------------------------------------------------------
// Dot product x_flat . w_mlp  -> g_acc  (block-tree reduce, 1 atomic/block)
__global__ void dot_kernel(const float4* __restrict__ w4) {
    // 2M floats = 512K float4; each thread handles a grid-stride of float4s
    const float4* x4 = reinterpret_cast<const float4*>(g_x);
    const int total4 = (N_NODES * H_DIM) / 4;
    float sum = 0.f;
    for (int i = blockIdx.x * blockDim.x + threadIdx.x; i < total4;
         i += gridDim.x * blockDim.x) {
        float4 a = x4[i];
        float4 b = w4[i];
        sum += a.x * b.x + a.y * b.y + a.z * b.z + a.w * b.w;
    }
    // warp reduce
    #pragma unroll
    for (int off = 16; off > 0; off >>= 1)
        sum += __shfl_down_sync(0xFFFFFFFFu, sum, off);
    __shared__ float warp_sums[8];
    int lane = threadIdx.x & 31, wid = threadIdx.x >> 5;
    if (lane == 0) warp_sums[wid] = sum;
    __syncthreads();
    if (wid == 0) {
        sum = (lane < (blockDim.x >> 5)) ? warp_sums[lane] : 0.f;
        #pragma unroll
        for (int off = 4; off > 0; off >>= 1)
            sum += __shfl_down_sync(0xFFFFFFFFu, sum, off);
        if (lane == 0) atomicAdd(&g_acc, sum);
    }
}

__global__ void finalize_kernel(const float* __restrict__ b_mlp,
                                float* __restrict__ out) {
    float logit = g_acc + b_mlp[0];
    out[0] = 1.f / (1.f + expf(-logit));
}

// ---------------------------------------------------------------------------
extern "C" void kernel_launch(void* const* d_in, const int* in_sizes, int n_in,
                              void* d_out, int out_size) {
    // metadata order == reference signature order
    const float* features  = (const float*)d_in[0];   // [N*H]
    const float* norm      = (const float*)d_in[1];   // [E,1]
    const float* V         = (const float*)d_in[2];   // [L,B,H,H]
    const float* comp      = (const float*)d_in[3];   // [L,R,B]
    const float* bias      = (const float*)d_in[4];   // [L,H]
    const float* w_mlp     = (const float*)d_in[5];   // [1,N*H]
    const float* b_mlp     = (const float*)d_in[6];   // [1]
    const int*   edge_src  = (const int*)d_in[7];     // [E]
    const int*   edge_dst  = (const int*)d_in[8];     // [E]
    const int*   edge_type = (const int*)d_in[9];     // [E]
    float*       out       = (float*)d_out;

    const int TB = 256;
    const int node_blocks = (N_NODES + TB - 1) / TB;
    const int edge_blocks = (E_EDGES / 4 + TB - 1) / TB;

    compute_weights_kernel<<<1, 64>>>(V, comp);
    init_x_kernel<<<node_blocks, TB>>>((const float2*)features);

    for (int l = 0; l < L_LAYERS; l++) {
        init_h_kernel<<<node_blocks, TB>>>(bias, l);
        edge_kernel<<<edge_blocks, TB>>>((const int4*)edge_src,
                                         (const int4*)edge_dst,
                                         (const int4*)edge_type,
                                         (const float4*)norm, l);
        node_kernel<<<node_blocks, TB>>>(l);
    }

    dot_kernel<<<1024, TB>>>((const float4*)w_mlp);
    finalize_kernel<<<1, 1>>>(b_mlp, out);
}